// round 1
// baseline (speedup 1.0000x reference)
#include <cuda_runtime.h>
#include <cstdint>

// Problem constants (fixed by setup_inputs)
#define SRATE 16000
#define NB 8
#define NH 100
#define NT 1000
#define NTS 80000   // NT * 80

// sin of the EXACT fp32 phase value ph (0 <= ph <= ~1.26e6), accurate to ~1e-6 abs.
// Cody-Waite reduction by pi/2 (2-term, FMA-exact products), quadrant fold, MUFU sin.
__device__ __forceinline__ float sin_arg_exact(float ph) {
    const float INV_PIO2 = 0.63661977236758134308f;            // fl(2/pi)
    const float MAGIC    = 12582912.0f;                        // 1.5 * 2^23
    const float P1       = 1.57079637050628662109375f;         // fl(pi/2)
    const float P2N      = 4.37113900018624283e-8f;            // -(pi/2 - P1)

    float kb = __fmaf_rn(ph, INV_PIO2, MAGIC);   // round-to-nearest int in mantissa
    int   q  = __float_as_int(kb);               // low 2 bits = k mod 4
    float kf = __fsub_rn(kb, MAGIC);             // k as exact float
    float r  = __fmaf_rn(kf, -P1, ph);           // exact product, single rounding
    r        = __fmaf_rn(kf,  P2N, r);           // |r| <= pi/4 + ~0.1, err ~5e-8

    // sin(k*pi/2 + r): fold quadrant bit0 as +pi/2, bit1 as sign flip.
    float off = (q & 1) ? P1 : 0.0f;
    float sv  = __sinf(__fadd_rn(r, off));       // RRO + MUFU.SIN, |arg| <= ~2.5
    // flip sign if q & 2 (sin(x+pi) = -sin(x))
    sv = __int_as_float(__float_as_int(sv) ^ ((q & 2) << 30));
    return sv;
}

__global__ __launch_bounds__(256)
void HarmonicOscillator_kernel(
    const float* __restrict__ f0,   // [B,1,T]
    const float* __restrict__ hd,   // [B,H,T]
    const float* __restrict__ ps,   // [B,1,T]
    float* __restrict__ out)        // [B,Ts]
{
    int s = blockIdx.x * blockDim.x + threadIdx.x;
    int b = blockIdx.y;
    if (s >= NTS) return;

    // --- interpolation grid (must match jnp fp32 rounding exactly) ---
    const float R = (float)(999.0 / 79999.0);    // (T-1)/(Ts-1), double->f32 like jax
    float sF  = (float)s;                        // exact
    float pos = __fmul_rn(sF, R);
    int i0 = (int)floorf(pos);
    if (i0 > NT - 2) i0 = NT - 2;
    float w = __fsub_rn(pos, (float)i0);

    // --- f0 / phase_shift interpolation: x0 + (x1-x0)*w, separate roundings ---
    const float* f0b = f0 + b * NT;
    const float* psb = ps + b * NT;
    float fa = __ldg(f0b + i0), fb = __ldg(f0b + i0 + 1);
    float f0u = __fadd_rn(fa, __fmul_rn(__fsub_rn(fb, fa), w));
    float pa = __ldg(psb + i0), pb = __ldg(psb + i0 + 1);
    float psu = __fadd_rn(pa, __fmul_rn(__fsub_rn(pb, pa), w));

    // base = fl(fl(c * f0u) * t), c = fl(2*pi/16000)
    const float C = (float)(2.0 * 3.14159265358979323846 / 16000.0);
    float base = __fmul_rn(__fmul_rn(C, f0u), sF);

    const float* hq = hd + (size_t)b * (NH * NT) + i0;

    float acc = 0.0f;
    float hF = 1.0f;
    #pragma unroll 5
    for (int h = 0; h < NH; ++h) {
        // phase = fl(fl(base*h) + ps)  — bit-exact vs reference
        float p   = __fmul_rn(base, hF);
        float phv = __fadd_rn(p, psu);
        float sv  = sin_arg_exact(phv);

        // harmonic_dist interpolation (precision non-critical: fma is fine)
        float x0 = __ldg(hq);
        float x1 = __ldg(hq + 1);
        float hdu = __fmaf_rn(__fsub_rn(x1, x0), w, x0);

        acc = __fmaf_rn(sv, hdu, acc);
        hF = __fadd_rn(hF, 1.0f);   // exact integer increments
        hq += NT;
    }

    out[(size_t)b * NTS + s] = acc;
}

extern "C" void kernel_launch(void* const* d_in, const int* in_sizes, int n_in,
                              void* d_out, int out_size) {
    const float* f0 = (const float*)d_in[0];
    const float* hd = (const float*)d_in[1];
    const float* ps = (const float*)d_in[2];
    float* out = (float*)d_out;

    dim3 block(256);
    dim3 grid((NTS + 255) / 256, NB);
    HarmonicOscillator_kernel<<<grid, block>>>(f0, hd, ps, out);
}

// round 2
// speedup vs baseline: 1.5102x; 1.5102x over previous
#include <cuda_runtime.h>
#include <cstdint>

// Problem constants (fixed by setup_inputs)
#define NB 8
#define NH 100
#define NT 1000
#define NTS 80000   // NT * 80
#define BLK 256

// Cody-Waite mod-2pi constants
#define INV2PI 0.15915494309189535f
#define MAGIC  12582912.0f                     // 1.5 * 2^23
#define TWOPI_HI 6.28318548202514648f          // fl(2*pi) = 0x40C90FDB
#define TWOPI_LO_NEG 1.7484555600e-7f          // -(2*pi - TWOPI_HI)

__global__ __launch_bounds__(BLK)
void HarmonicOscillator_kernel(
    const float* __restrict__ f0,   // [B,1,T]
    const float* __restrict__ hd,   // [B,H,T]
    const float* __restrict__ ps,   // [B,1,T]
    float* __restrict__ out)        // [B,Ts]
{
    // pairs[h][j] = (hd[b][h][j0+j], hd[b][h][j0+j+1]) for the block's i0 window
    __shared__ float2 pairs[NH * 5];

    const int s0 = blockIdx.x * BLK;
    const int b  = blockIdx.y;
    const int s  = s0 + threadIdx.x;

    const float R = (float)(999.0 / 79999.0);   // (T-1)/(Ts-1) rounded like jax f32

    // Block-uniform window start: i0 is monotone in s, spans <= 4 ints over 256 samples
    int j0 = (int)__fmul_rn((float)s0, R);
    if (j0 > NT - 2) j0 = NT - 2;

    // --- cooperative smem fill: 500 float2 entries ---
    {
        const float* hb = hd + (size_t)b * (NH * NT);
        for (int idx = threadIdx.x; idx < NH * 5; idx += BLK) {
            int h = idx / 5;
            int j = idx - h * 5;
            int g0 = j0 + j;     if (g0 > NT - 1) g0 = NT - 1;
            int g1 = g0 + 1;     if (g1 > NT - 1) g1 = NT - 1;
            pairs[idx] = make_float2(__ldg(hb + h * NT + g0), __ldg(hb + h * NT + g1));
        }
    }
    __syncthreads();

    if (s >= NTS) return;

    // --- per-thread interpolation coords (match jnp f32 rounding exactly) ---
    float sF  = (float)s;
    float pos = __fmul_rn(sF, R);
    int i0 = (int)pos;                   // pos >= 0 -> trunc == floor
    if (i0 > NT - 2) i0 = NT - 2;
    float w = __fsub_rn(pos, (float)i0);
    int li = i0 - j0;                    // 0..4

    // --- f0 / phase_shift interp: x0 + (x1-x0)*w, separate roundings ---
    const float* f0b = f0 + b * NT;
    const float* psb = ps + b * NT;
    float fa = __ldg(f0b + i0), fb = __ldg(f0b + i0 + 1);
    float f0u = __fadd_rn(fa, __fmul_rn(__fsub_rn(fb, fa), w));
    float pa = __ldg(psb + i0), pb = __ldg(psb + i0 + 1);
    float psu = __fadd_rn(pa, __fmul_rn(__fsub_rn(pb, pa), w));

    // base = fl(fl(C * f0u) * t), C = fl(2*pi/16000)
    const float C = (float)(2.0 * 3.14159265358979323846 / 16000.0);
    float base = __fmul_rn(__fmul_rn(C, f0u), sF);

    const float2* sp = pairs + li;

    float acc = 0.0f;
    #pragma unroll
    for (int h = 0; h < NH; ++h) {
        // X = fl(fl(base*(h+1)) + psu) -- bit-exact vs reference phase
        float p = __fmul_rn(base, (float)(h + 1));   // FMUL-imm
        float X = __fadd_rn(p, psu);

        // reduce X mod 2*pi (k < 2^18): r in [-pi-0.04, pi+0.04], err ~2.5e-7 rad
        float kb = __fmaf_rn(X, INV2PI, MAGIC);
        float kf = __fsub_rn(kb, MAGIC);
        float r  = __fmaf_rn(kf, -TWOPI_HI, X);
        r        = __fmaf_rn(kf,  TWOPI_LO_NEG, r);
        float sv = __sinf(r);

        // harmonic_dist interp from staged pairs (one LDS.64)
        float2 v = sp[h * 5];
        float hdu = __fmaf_rn(__fsub_rn(v.y, v.x), w, v.x);

        acc = __fmaf_rn(sv, hdu, acc);
    }

    out[(size_t)b * NTS + s] = acc;
}

extern "C" void kernel_launch(void* const* d_in, const int* in_sizes, int n_in,
                              void* d_out, int out_size) {
    const float* f0 = (const float*)d_in[0];
    const float* hd = (const float*)d_in[1];
    const float* ps = (const float*)d_in[2];
    float* out = (float*)d_out;

    dim3 block(BLK);
    dim3 grid((NTS + BLK - 1) / BLK, NB);
    HarmonicOscillator_kernel<<<grid, block>>>(f0, hd, ps, out);
}

// round 3
// speedup vs baseline: 1.7488x; 1.1580x over previous
#include <cuda_runtime.h>
#include <cstdint>

// Problem constants (fixed by setup_inputs)
#define NB 8
#define NH 100
#define NT 1000
#define NTS 80000   // NT * 80
#define BLK 256
#define NH2 (NH / 2)   // 50 harmonic pairs

// Cody-Waite mod-2pi constants
#define INV2PI 0.15915494309189535f
#define MAGIC  12582912.0f                     // 1.5 * 2^23
#define TWOPI_HI 6.28318548202514648f          // fl(2*pi) = 0x40C90FDB
#define TWOPI_LO_NEG 1.7484555600e-7f          // -(2*pi - TWOPI_HI)

__device__ __forceinline__ float sin_mod2pi(float X) {
    float kb = __fmaf_rn(X, INV2PI, MAGIC);    // round(X/2pi) in mantissa
    float kf = __fsub_rn(kb, MAGIC);           // exact k as float (k < 2^18)
    float r  = __fmaf_rn(kf, -TWOPI_HI, X);
    r        = __fmaf_rn(kf,  TWOPI_LO_NEG, r);
    return __sinf(r);                          // |r| <= pi + eps
}

__global__ __launch_bounds__(BLK)
void HarmonicOscillator_kernel(
    const float* __restrict__ f0,   // [B,1,T]
    const float* __restrict__ hd,   // [B,H,T]
    const float* __restrict__ ps,   // [B,1,T]
    float* __restrict__ out)        // [B,Ts]
{
    // q[h2*5 + li] = (x0_{2h2}, d_{2h2}, x0_{2h2+1}, d_{2h2+1}) at grid col j0+li
    __shared__ float4 q[NH2 * 5];

    const int s0 = blockIdx.x * BLK;
    const int b  = blockIdx.y;
    const int s  = s0 + threadIdx.x;

    const float R = (float)(999.0 / 79999.0);   // (T-1)/(Ts-1) rounded like jax f32

    // Block-uniform window start (i0 monotone; spans <=5 values over 256 samples)
    int j0 = (int)__fmul_rn((float)s0, R);
    if (j0 > NT - 2) j0 = NT - 2;

    // --- cooperative smem fill: 250 float4 entries (2 harmonics each) ---
    {
        const float* hb = hd + (size_t)b * (NH * NT);
        for (int idx = threadIdx.x; idx < NH2 * 5; idx += BLK) {
            int h2 = idx / 5;
            int j  = idx - h2 * 5;
            int g0 = j0 + j;  if (g0 > NT - 1) g0 = NT - 1;
            int g1 = g0 + 1;  if (g1 > NT - 1) g1 = NT - 1;
            const float* r0 = hb + (2 * h2) * NT;
            const float* r1 = r0 + NT;
            float a0 = __ldg(r0 + g0), a1 = __ldg(r0 + g1);
            float b0 = __ldg(r1 + g0), b1 = __ldg(r1 + g1);
            q[idx] = make_float4(a0, __fsub_rn(a1, a0), b0, __fsub_rn(b1, b0));
        }
    }
    __syncthreads();

    if (s >= NTS) return;

    // --- per-thread interpolation coords (match jnp f32 rounding exactly) ---
    float sF  = (float)s;
    float pos = __fmul_rn(sF, R);
    int i0 = (int)pos;                   // pos >= 0 -> trunc == floor
    if (i0 > NT - 2) i0 = NT - 2;
    float w = __fsub_rn(pos, (float)i0);
    int li = i0 - j0;                    // 0..4

    // --- f0 / phase_shift interp: x0 + (x1-x0)*w, separate roundings ---
    const float* f0b = f0 + b * NT;
    const float* psb = ps + b * NT;
    float fa = __ldg(f0b + i0), fb = __ldg(f0b + i0 + 1);
    float f0u = __fadd_rn(fa, __fmul_rn(__fsub_rn(fb, fa), w));
    float pa = __ldg(psb + i0), pb = __ldg(psb + i0 + 1);
    float psu = __fadd_rn(pa, __fmul_rn(__fsub_rn(pb, pa), w));

    // base = fl(fl(C * f0u) * t), C = fl(2*pi/16000)
    const float C = (float)(2.0 * 3.14159265358979323846 / 16000.0);
    float base = __fmul_rn(__fmul_rn(C, f0u), sF);

    const float4* qp = q + li;

    float acc0 = 0.0f, acc1 = 0.0f;
    #pragma unroll
    for (int h2 = 0; h2 < NH2; ++h2) {
        float4 v = qp[h2 * 5];                       // one LDS.128, 2 harmonics

        // harmonic 2*h2+1
        float p0 = __fmul_rn(base, (float)(2 * h2 + 1));  // FMUL-imm
        float X0 = __fadd_rn(p0, psu);                     // bit-exact ref phase
        float s0v = sin_mod2pi(X0);
        acc0 = __fmaf_rn(s0v, __fmaf_rn(v.y, w, v.x), acc0);

        // harmonic 2*h2+2
        float p1 = __fmul_rn(base, (float)(2 * h2 + 2));
        float X1 = __fadd_rn(p1, psu);
        float s1v = sin_mod2pi(X1);
        acc1 = __fmaf_rn(s1v, __fmaf_rn(v.w, w, v.z), acc1);
    }

    out[(size_t)b * NTS + s] = __fadd_rn(acc0, acc1);
}

extern "C" void kernel_launch(void* const* d_in, const int* in_sizes, int n_in,
                              void* d_out, int out_size) {
    const float* f0 = (const float*)d_in[0];
    const float* hd = (const float*)d_in[1];
    const float* ps = (const float*)d_in[2];
    float* out = (float*)d_out;

    dim3 block(BLK);
    dim3 grid((NTS + BLK - 1) / BLK, NB);
    HarmonicOscillator_kernel<<<grid, block>>>(f0, hd, ps, out);
}